// round 6
// baseline (speedup 1.0000x reference)
#include <cuda_runtime.h>
#include <math.h>

#define BATCH 8192
#define CH 128
#define NB 32
#define NH 4
#define HD 32
#define O3 384
#define ATT_SCALE 0.17677669529663687f  // 1/sqrt(32)

typedef unsigned long long u64;

__device__ __forceinline__ u64 pack2(float lo, float hi) {
    u64 r; asm("mov.b64 %0, {%1, %2};" : "=l"(r) : "f"(lo), "f"(hi)); return r;
}
__device__ __forceinline__ void unpack2(u64 v, float& lo, float& hi) {
    asm("mov.b64 {%0, %1}, %2;" : "=f"(lo), "=f"(hi) : "l"(v));
}
__device__ __forceinline__ u64 ffma2(u64 a, u64 b, u64 c) {
    u64 d; asm("fma.rn.f32x2 %0, %1, %2, %3;" : "=l"(d) : "l"(a), "l"(b), "l"(c)); return d;
}
__device__ __forceinline__ u64 fadd2(u64 a, u64 b) {
    u64 d; asm("add.rn.f32x2 %0, %1, %2;" : "=l"(d) : "l"(a), "l"(b)); return d;
}

// ---- device scratch (no allocations allowed) ----
// Weights stored PRE-DUPLICATED as u64 {w,w}: one LDG.64, zero packing movs.
__device__ u64    g_qkv_w2[CH * O3];   // [c][o] -> {w,w}
__device__ u64    g_out_w2[CH * CH];   // [c][o] -> {w,w}
__device__ double g_bn_sum[CH];
__device__ double g_bn_sqs[CH];
__device__ float  g_bn_g[CH];
__device__ float  g_bn_b[CH];

__global__ void prep_kernel(const float* __restrict__ qkv_w,
                            const float* __restrict__ out_w) {
    int i = blockIdx.x * blockDim.x + threadIdx.x;
    if (i < O3 * CH) {
        int o = i / CH, c = i % CH;
        float w = qkv_w[i];
        g_qkv_w2[c * O3 + o] = pack2(w, w);
    }
    if (i < CH * CH) {
        int o = i / CH, c = i % CH;
        float w = out_w[i];
        g_out_w2[c * CH + o] = pack2(w, w);
    }
    if (i < CH) { g_bn_sum[i] = 0.0; g_bn_sqs[i] = 0.0; }
}

// Shared memory (floats), row stride 36 = 144B (16B aligned rows).
//  xs [128][36]  x[b] staged; DEAD after Phase A -> reused as ao in Phase C
//  kv k [128][36] rows (h*32+d); v [128][36]
//  rp [4][63]
// q tile lives in d_out[b] (gmem scratch, overwritten by final y in Phase D).
#define XS_OFF   0
#define KK_OFF   4608
#define VV_OFF   9216
#define RP_OFF   13824
#define SMEM_FLOATS 14080   // 56,320 bytes -> 4 CTAs/SM

__global__ void __launch_bounds__(128, 4)
attn_kernel(const float* __restrict__ x,
            const float* __restrict__ qkv_b,
            const float* __restrict__ out_b,
            const float* __restrict__ remb,
            float* out) {
    extern __shared__ float sm[];
    float* xs = sm + XS_OFF;
    float* kk = sm + KK_OFF;
    float* vv = sm + VV_OFF;
    float* ao = sm + XS_OFF;   // aliases xs (dead after Phase A)
    float* rp = sm + RP_OFF;

    const int tid  = threadIdx.x;
    const int lane = tid & 31;
    const int wid  = tid >> 5;
    const int b    = blockIdx.x;

    float* gb = out + (size_t)b * (CH * NB);          // per-batch out region (q scratch, then y)
    const float* xb = x + (size_t)b * (CH * NB);

    // ---- stage x[b] into smem ----
    const float4* xg = (const float4*)xb;
#pragma unroll
    for (int k = 0; k < 8; k++) {
        int f = tid + k * 128;
        float4 v = xg[f];
        int c = f >> 3, n4 = f & 7;
        *(float4*)(xs + c * 36 + n4 * 4) = v;
    }
    for (int i = tid; i < (2 * NB - 1) * NH; i += 128) {
        int p = i >> 2, h = i & 3;
        rp[h * 63 + p] = remb[i];
    }
    __syncthreads();

    // ---- Phase A (fused q/k/v): one pass over c; 8 LDS feed 48 FFMA2 ----
    {
        const int o = wid * 32 + lane;           // q row; k = o+128; v = o+256 in W
        u64 accq[16], acck[16], accv[16];
        {
            float bq = qkv_b[o], bk = qkv_b[o + 128], bv = qkv_b[o + 256];
            u64 q2 = pack2(bq, bq), k2 = pack2(bk, bk), v2 = pack2(bv, bv);
#pragma unroll
            for (int j = 0; j < 16; j++) { accq[j] = q2; acck[j] = k2; accv[j] = v2; }
        }
#pragma unroll 2
        for (int c = 0; c < CH; c++) {
            u64 wq = g_qkv_w2[c * O3 + o];             // coalesced LDG.64 (L2)
            u64 wk = g_qkv_w2[c * O3 + o + 128];
            u64 wv = g_qkv_w2[c * O3 + o + 256];
            const ulonglong2* xr = (const ulonglong2*)(xs + c * 36); // LDS.128 broadcast
#pragma unroll
            for (int j = 0; j < 8; j++) {
                ulonglong2 xv = xr[j];
                accq[2*j+0] = ffma2(wq, xv.x, accq[2*j+0]);
                accq[2*j+1] = ffma2(wq, xv.y, accq[2*j+1]);
                acck[2*j+0] = ffma2(wk, xv.x, acck[2*j+0]);
                acck[2*j+1] = ffma2(wk, xv.y, acck[2*j+1]);
                accv[2*j+0] = ffma2(wv, xv.x, accv[2*j+0]);
                accv[2*j+1] = ffma2(wv, xv.y, accv[2*j+1]);
            }
        }
        // q -> gmem scratch (out[b], row o: 128B contiguous per thread)
        ulonglong2* gq = (ulonglong2*)(gb + o * 32);
        ulonglong2* dk = (ulonglong2*)(kk + o * 36);
        ulonglong2* dv = (ulonglong2*)(vv + o * 36);
#pragma unroll
        for (int j = 0; j < 8; j++) {
            gq[j] = make_ulonglong2(accq[2*j], accq[2*j+1]);
            dk[j] = make_ulonglong2(acck[2*j], acck[2*j+1]);
            dv[j] = make_ulonglong2(accv[2*j], accv[2*j+1]);
        }
    }
    __syncthreads();   // orders q gmem writes + k/v smem for all warps

    // ---- Phase B: head h = wid, query bin n = lane ----
    {
        int h = wid;
        float qreg[32];
#pragma unroll
        for (int d = 0; d < 32; d++)
            qreg[d] = gb[(h * 32 + d) * 32 + lane];   // coalesced LDG, L2 hit
        u64 att2[16];
#pragma unroll
        for (int j = 0; j < 16; j++) att2[j] = 0ull;
#pragma unroll 4
        for (int d = 0; d < 32; d++) {
            u64 qd2 = pack2(qreg[d], qreg[d]);
            const ulonglong2* kr = (const ulonglong2*)(kk + (h * 32 + d) * 36);
#pragma unroll
            for (int j = 0; j < 8; j++) {
                ulonglong2 kv = kr[j];
                att2[2*j+0] = ffma2(qd2, kv.x, att2[2*j+0]);
                att2[2*j+1] = ffma2(qd2, kv.y, att2[2*j+1]);
            }
        }
        float att[32];
#pragma unroll
        for (int j = 0; j < 16; j++) unpack2(att2[j], att[2*j], att[2*j+1]);
#pragma unroll
        for (int m = 0; m < 32; m++) {
            int idx = m - lane + (NB - 1);
            idx = idx < 0 ? 0 : (idx > 2 * NB - 2 ? 2 * NB - 2 : idx);
            att[m] = fmaf(att[m], ATT_SCALE, rp[h * 63 + idx]);
        }
        float mx = att[0];
#pragma unroll
        for (int m = 1; m < 32; m++) mx = fmaxf(mx, att[m]);
        float ssum = 0.0f;
#pragma unroll
        for (int m = 0; m < 32; m++) {
            float e = __expf(att[m] - mx);
            att[m] = e;
            ssum += e;
        }
        float rs = 1.0f / ssum;
#pragma unroll
        for (int m = 0; m < 32; m++) att[m] *= rs;
#pragma unroll
        for (int j = 0; j < 16; j++) att2[j] = pack2(att[2*j], att[2*j+1]);

        // ---- Phase C: ao[h*32+d][n] = sum_m att[m] * v[h,d,m] ----
        // ao aliases xs (dead since the post-Phase-A barrier).
#pragma unroll 2
        for (int d = 0; d < 32; d++) {
            const ulonglong2* vr = (const ulonglong2*)(vv + (h * 32 + d) * 36);
            u64 sa = 0ull, sb = 0ull;
#pragma unroll
            for (int j = 0; j < 8; j++) {
                ulonglong2 vx = vr[j];
                sa = ffma2(att2[2*j+0], vx.x, sa);
                sb = ffma2(att2[2*j+1], vx.y, sb);
            }
            float a0, a1, b0, b1;
            unpack2(sa, a0, a1); unpack2(sb, b0, b1);
            ao[(h * 32 + d) * 36 + lane] = (a0 + a1) + (b0 + b1);
        }
    }
    __syncthreads();   // all q-reads done; ao complete

    // ---- Phase D: y = out_w @ ao + out_b + x ; BN stats ; direct gmem write ----
    {
        int o = tid;
        float ob = out_b[o];
        u64 acc2[16];
        u64 ob2 = pack2(ob, ob);
#pragma unroll
        for (int j = 0; j < 16; j++) acc2[j] = ob2;
#pragma unroll 8
        for (int c = 0; c < CH; c++) {
            u64 w2 = g_out_w2[c * CH + o];                       // LDG.64 (L2)
            const ulonglong2* ar = (const ulonglong2*)(ao + c * 36);
#pragma unroll
            for (int j = 0; j < 8; j++) {
                ulonglong2 av = ar[j];
                acc2[2*j+0] = ffma2(w2, av.x, acc2[2*j+0]);
                acc2[2*j+1] = ffma2(w2, av.y, acc2[2*j+1]);
            }
        }
        u64 s1_2 = 0ull, s2_2 = 0ull;
        const ulonglong2* xr = (const ulonglong2*)(xb + o * 32);  // residual from gmem (L2)
        ulonglong2* yd = (ulonglong2*)(gb + o * 32);              // overwrite q scratch with y
#pragma unroll
        for (int j = 0; j < 8; j++) {
            ulonglong2 xv = xr[j];
            u64 y0 = fadd2(acc2[2*j+0], xv.x);
            u64 y1 = fadd2(acc2[2*j+1], xv.y);
            s1_2 = fadd2(s1_2, fadd2(y0, y1));
            s2_2 = ffma2(y0, y0, s2_2);
            s2_2 = ffma2(y1, y1, s2_2);
            yd[j] = make_ulonglong2(y0, y1);
        }
        float p0, p1, q0, q1;
        unpack2(s1_2, p0, p1); unpack2(s2_2, q0, q1);
        atomicAdd(&g_bn_sum[o], (double)(p0 + p1));
        atomicAdd(&g_bn_sqs[o], (double)(q0 + q1));
    }
}

__global__ void bn_finalize(const float* __restrict__ gamma,
                            const float* __restrict__ beta) {
    int c = threadIdx.x;
    const double cnt = (double)BATCH * NB;
    double mean = g_bn_sum[c] / cnt;
    double var  = g_bn_sqs[c] / cnt - mean * mean;
    double inv  = 1.0 / sqrt(var + 1e-5);
    double g = (double)gamma[c] * inv;
    g_bn_g[c] = (float)g;
    g_bn_b[c] = (float)((double)beta[c] - mean * g);
}

__global__ void bn_apply(float* __restrict__ out) {
    int i = blockIdx.x * blockDim.x + threadIdx.x;
    float4 v = ((const float4*)out)[i];
    int c = (i >> 3) & 127;
    float g = g_bn_g[c], b = g_bn_b[c];
    v.x = fmaf(v.x, g, b);
    v.y = fmaf(v.y, g, b);
    v.z = fmaf(v.z, g, b);
    v.w = fmaf(v.w, g, b);
    ((float4*)out)[i] = v;
}

extern "C" void kernel_launch(void* const* d_in, const int* in_sizes, int n_in,
                              void* d_out, int out_size) {
    const float* x      = (const float*)d_in[0];
    const float* qkv_w  = (const float*)d_in[1];
    const float* qkv_b  = (const float*)d_in[2];
    const float* out_w  = (const float*)d_in[3];
    const float* out_b  = (const float*)d_in[4];
    const float* remb   = (const float*)d_in[5];
    const float* gamma  = (const float*)d_in[6];
    const float* beta   = (const float*)d_in[7];
    float* out = (float*)d_out;

    cudaFuncSetAttribute(attn_kernel, cudaFuncAttributeMaxDynamicSharedMemorySize,
                         SMEM_FLOATS * (int)sizeof(float));

    prep_kernel<<<192, 256>>>(qkv_w, out_w);
    attn_kernel<<<BATCH, 128, SMEM_FLOATS * sizeof(float)>>>(x, qkv_b, out_b, remb, out);
    bn_finalize<<<1, CH>>>(gamma, beta);
    bn_apply<<<(BATCH * CH * NB / 4) / 256, 256>>>(out);
}

// round 7
// speedup vs baseline: 1.6158x; 1.6158x over previous
#include <cuda_runtime.h>
#include <math.h>

#define BATCH 8192
#define CH 128
#define NB 32
#define NH 4
#define HD 32
#define O3 384
#define ATT_SCALE 0.17677669529663687f  // 1/sqrt(32)

typedef unsigned long long u64;

__device__ __forceinline__ u64 pack2(float lo, float hi) {
    u64 r; asm("mov.b64 %0, {%1, %2};" : "=l"(r) : "f"(lo), "f"(hi)); return r;
}
__device__ __forceinline__ void unpack2(u64 v, float& lo, float& hi) {
    asm("mov.b64 {%0, %1}, %2;" : "=f"(lo), "=f"(hi) : "l"(v));
}
__device__ __forceinline__ u64 ffma2(u64 a, u64 b, u64 c) {
    u64 d; asm("fma.rn.f32x2 %0, %1, %2, %3;" : "=l"(d) : "l"(a), "l"(b), "l"(c)); return d;
}
__device__ __forceinline__ u64 fadd2(u64 a, u64 b) {
    u64 d; asm("add.rn.f32x2 %0, %1, %2;" : "=l"(d) : "l"(a), "l"(b)); return d;
}

// ---- device scratch (no allocations allowed) ----
__device__ u64    g_qkv_w2[CH * O3];   // [c][o] -> {w,w}
__device__ u64    g_out_w2[CH * CH];   // [c][o] -> {w,w}
__device__ double g_bn_sum[CH];
__device__ double g_bn_sqs[CH];
__device__ float  g_bn_g[CH];
__device__ float  g_bn_b[CH];

__global__ void prep_kernel(const float* __restrict__ qkv_w,
                            const float* __restrict__ out_w) {
    int i = blockIdx.x * blockDim.x + threadIdx.x;
    if (i < O3 * CH) {
        int o = i / CH, c = i % CH;
        float w = qkv_w[i];
        g_qkv_w2[c * O3 + o] = pack2(w, w);
    }
    if (i < CH * CH) {
        int o = i / CH, c = i % CH;
        float w = out_w[i];
        g_out_w2[c * CH + o] = pack2(w, w);
    }
    if (i < CH) { g_bn_sum[i] = 0.0; g_bn_sqs[i] = 0.0; }
}

// Shared memory (floats), row stride 36 = 144B.
//  xs [128][36]  x[b]; DEAD after Phase A -> reused as ao
//  kk [128][36]  k rows (h*32+d);  vv [128][36]  v rows
//  rp [4][63]
// q tile lives in d_out[b] (gmem scratch, overwritten by final y in Phase D).
#define XS_OFF   0
#define KK_OFF   4608
#define VV_OFF   9216
#define RP_OFF   13824
#define SMEM_FLOATS 14080   // 56,320 bytes -> 4 CTAs/SM

__global__ void __launch_bounds__(128, 4)
attn_kernel(const float* __restrict__ x,
            const float* __restrict__ qkv_b,
            const float* __restrict__ out_b,
            const float* __restrict__ remb,
            float* out) {
    extern __shared__ float sm[];
    float* xs = sm + XS_OFF;
    float* kk = sm + KK_OFF;
    float* vv = sm + VV_OFF;
    float* ao = sm + XS_OFF;   // aliases xs (dead after Phase A)
    float* rp = sm + RP_OFF;

    const int tid  = threadIdx.x;
    const int lane = tid & 31;
    const int wid  = tid >> 5;
    const int b    = blockIdx.x;

    float* gb = out + (size_t)b * (CH * NB);          // q scratch, then final y
    const float* xb = x + (size_t)b * (CH * NB);

    // ---- stage x[b] into smem ----
    const float4* xg = (const float4*)xb;
#pragma unroll
    for (int k = 0; k < 8; k++) {
        int f = tid + k * 128;
        float4 v = xg[f];
        int c = f >> 3, n4 = f & 7;
        *(float4*)(xs + c * 36 + n4 * 4) = v;
    }
    for (int i = tid; i < (2 * NB - 1) * NH; i += 128) {
        int p = i >> 2, h = i & 3;
        rp[h * 63 + p] = remb[i];
    }
    __syncthreads();

    const int o = wid * 32 + lane;   // this thread's output row (q / k / v / y)

    // ---- Phase A pass 1: q + k fused (64 acc regs — fits 128-reg cap) ----
    {
        u64 accq[16], acck[16];
        {
            float bq = qkv_b[o], bk = qkv_b[o + 128];
            u64 q2 = pack2(bq, bq), k2 = pack2(bk, bk);
#pragma unroll
            for (int j = 0; j < 16; j++) { accq[j] = q2; acck[j] = k2; }
        }
#pragma unroll 2
        for (int c = 0; c < CH; c++) {
            u64 wq = g_qkv_w2[c * O3 + o];             // coalesced LDG.64 (L2)
            u64 wk = g_qkv_w2[c * O3 + o + 128];
            const ulonglong2* xr = (const ulonglong2*)(xs + c * 36); // LDS.128 bcast
#pragma unroll
            for (int j = 0; j < 8; j++) {
                ulonglong2 xv = xr[j];
                accq[2*j+0] = ffma2(wq, xv.x, accq[2*j+0]);
                accq[2*j+1] = ffma2(wq, xv.y, accq[2*j+1]);
                acck[2*j+0] = ffma2(wk, xv.x, acck[2*j+0]);
                acck[2*j+1] = ffma2(wk, xv.y, acck[2*j+1]);
            }
        }
        ulonglong2* gq = (ulonglong2*)(gb + o * 32);   // q -> gmem scratch
        ulonglong2* dk = (ulonglong2*)(kk + o * 36);
#pragma unroll
        for (int j = 0; j < 8; j++) {
            gq[j] = make_ulonglong2(accq[2*j], accq[2*j+1]);
            dk[j] = make_ulonglong2(acck[2*j], acck[2*j+1]);
        }
    }

    // ---- Phase A pass 2: v (32 acc regs) ----
    {
        u64 accv[16];
        {
            float bv = qkv_b[o + 256];
            u64 v2 = pack2(bv, bv);
#pragma unroll
            for (int j = 0; j < 16; j++) accv[j] = v2;
        }
#pragma unroll 2
        for (int c = 0; c < CH; c++) {
            u64 wv = g_qkv_w2[c * O3 + o + 256];
            const ulonglong2* xr = (const ulonglong2*)(xs + c * 36);
#pragma unroll
            for (int j = 0; j < 8; j++) {
                ulonglong2 xv = xr[j];
                accv[2*j+0] = ffma2(wv, xv.x, accv[2*j+0]);
                accv[2*j+1] = ffma2(wv, xv.y, accv[2*j+1]);
            }
        }
        ulonglong2* dv = (ulonglong2*)(vv + o * 36);
#pragma unroll
        for (int j = 0; j < 8; j++)
            dv[j] = make_ulonglong2(accv[2*j], accv[2*j+1]);
    }
    __syncthreads();   // k/v smem + q gmem visible block-wide; xs now dead

    // ---- Phase B: head h = wid, query bin n = lane ----
    {
        int h = wid;
        float qreg[32];
#pragma unroll
        for (int d = 0; d < 32; d++)
            qreg[d] = gb[(h * 32 + d) * 32 + lane];   // coalesced LDG, L2 hit
        u64 att2[16];
#pragma unroll
        for (int j = 0; j < 16; j++) att2[j] = 0ull;
#pragma unroll 4
        for (int d = 0; d < 32; d++) {
            u64 qd2 = pack2(qreg[d], qreg[d]);
            const ulonglong2* kr = (const ulonglong2*)(kk + (h * 32 + d) * 36);
#pragma unroll
            for (int j = 0; j < 8; j++) {
                ulonglong2 kv = kr[j];
                att2[2*j+0] = ffma2(qd2, kv.x, att2[2*j+0]);
                att2[2*j+1] = ffma2(qd2, kv.y, att2[2*j+1]);
            }
        }
        float att[32];
#pragma unroll
        for (int j = 0; j < 16; j++) unpack2(att2[j], att[2*j], att[2*j+1]);
#pragma unroll
        for (int m = 0; m < 32; m++) {
            int idx = m - lane + (NB - 1);
            idx = idx < 0 ? 0 : (idx > 2 * NB - 2 ? 2 * NB - 2 : idx);
            att[m] = fmaf(att[m], ATT_SCALE, rp[h * 63 + idx]);
        }
        float mx = att[0];
#pragma unroll
        for (int m = 1; m < 32; m++) mx = fmaxf(mx, att[m]);
        float ssum = 0.0f;
#pragma unroll
        for (int m = 0; m < 32; m++) {
            float e = __expf(att[m] - mx);
            att[m] = e;
            ssum += e;
        }
        float rs = 1.0f / ssum;
#pragma unroll
        for (int m = 0; m < 32; m++) att[m] *= rs;
#pragma unroll
        for (int j = 0; j < 16; j++) att2[j] = pack2(att[2*j], att[2*j+1]);

        // ---- Phase C: ao[h*32+d][n] = sum_m att[m] * v[h,d,m] ----
#pragma unroll 2
        for (int d = 0; d < 32; d++) {
            const ulonglong2* vr = (const ulonglong2*)(vv + (h * 32 + d) * 36);
            u64 sa = 0ull, sb = 0ull;
#pragma unroll
            for (int j = 0; j < 8; j++) {
                ulonglong2 vx = vr[j];
                sa = ffma2(att2[2*j+0], vx.x, sa);
                sb = ffma2(att2[2*j+1], vx.y, sb);
            }
            float a0, a1, b0, b1;
            unpack2(sa, a0, a1); unpack2(sb, b0, b1);
            ao[(h * 32 + d) * 36 + lane] = (a0 + a1) + (b0 + b1);
        }
    }
    __syncthreads();   // all q-reads done; ao complete

    // ---- Phase D: y = out_w @ ao + out_b + x ; BN stats ; direct gmem write ----
    {
        float ob = out_b[tid];
        u64 acc2[16];
        u64 ob2 = pack2(ob, ob);
#pragma unroll
        for (int j = 0; j < 16; j++) acc2[j] = ob2;
#pragma unroll 8
        for (int c = 0; c < CH; c++) {
            u64 w2 = g_out_w2[c * CH + tid];                     // LDG.64 (L2)
            const ulonglong2* ar = (const ulonglong2*)(ao + c * 36);
#pragma unroll
            for (int j = 0; j < 8; j++) {
                ulonglong2 av = ar[j];
                acc2[2*j+0] = ffma2(w2, av.x, acc2[2*j+0]);
                acc2[2*j+1] = ffma2(w2, av.y, acc2[2*j+1]);
            }
        }
        u64 s1_2 = 0ull, s2_2 = 0ull;
        const ulonglong2* xr = (const ulonglong2*)(xb + tid * 32); // residual (L2)
        ulonglong2* yd = (ulonglong2*)(gb + tid * 32);             // overwrite scratch
#pragma unroll
        for (int j = 0; j < 8; j++) {
            ulonglong2 xv = xr[j];
            u64 y0 = fadd2(acc2[2*j+0], xv.x);
            u64 y1 = fadd2(acc2[2*j+1], xv.y);
            s1_2 = fadd2(s1_2, fadd2(y0, y1));
            s2_2 = ffma2(y0, y0, s2_2);
            s2_2 = ffma2(y1, y1, s2_2);
            yd[j] = make_ulonglong2(y0, y1);
        }
        float p0, p1, q0, q1;
        unpack2(s1_2, p0, p1); unpack2(s2_2, q0, q1);
        atomicAdd(&g_bn_sum[tid], (double)(p0 + p1));
        atomicAdd(&g_bn_sqs[tid], (double)(q0 + q1));
    }
}

__global__ void bn_finalize(const float* __restrict__ gamma,
                            const float* __restrict__ beta) {
    int c = threadIdx.x;
    const double cnt = (double)BATCH * NB;
    double mean = g_bn_sum[c] / cnt;
    double var  = g_bn_sqs[c] / cnt - mean * mean;
    double inv  = 1.0 / sqrt(var + 1e-5);
    double g = (double)gamma[c] * inv;
    g_bn_g[c] = (float)g;
    g_bn_b[c] = (float)((double)beta[c] - mean * g);
}

__global__ void bn_apply(float* __restrict__ out) {
    int i = blockIdx.x * blockDim.x + threadIdx.x;
    float4 v = ((const float4*)out)[i];
    int c = (i >> 3) & 127;
    float g = g_bn_g[c], b = g_bn_b[c];
    v.x = fmaf(v.x, g, b);
    v.y = fmaf(v.y, g, b);
    v.z = fmaf(v.z, g, b);
    v.w = fmaf(v.w, g, b);
    ((float4*)out)[i] = v;
}

extern "C" void kernel_launch(void* const* d_in, const int* in_sizes, int n_in,
                              void* d_out, int out_size) {
    const float* x      = (const float*)d_in[0];
    const float* qkv_w  = (const float*)d_in[1];
    const float* qkv_b  = (const float*)d_in[2];
    const float* out_w  = (const float*)d_in[3];
    const float* out_b  = (const float*)d_in[4];
    const float* remb   = (const float*)d_in[5];
    const float* gamma  = (const float*)d_in[6];
    const float* beta   = (const float*)d_in[7];
    float* out = (float*)d_out;

    cudaFuncSetAttribute(attn_kernel, cudaFuncAttributeMaxDynamicSharedMemorySize,
                         SMEM_FLOATS * (int)sizeof(float));

    prep_kernel<<<192, 256>>>(qkv_w, out_w);
    attn_kernel<<<BATCH, 128, SMEM_FLOATS * sizeof(float)>>>(x, qkv_b, out_b, remb, out);
    bn_finalize<<<1, CH>>>(gamma, beta);
    bn_apply<<<(BATCH * CH * NB / 4) / 256, 256>>>(out);
}

// round 8
// speedup vs baseline: 1.8233x; 1.1284x over previous
#include <cuda_runtime.h>
#include <math.h>

#define BATCH 8192
#define CH 128
#define NB 32
#define NH 4
#define HD 32
#define O3 384
#define ATT_SCALE 0.17677669529663687f  // 1/sqrt(32)

typedef unsigned long long u64;

__device__ __forceinline__ u64 pack2(float lo, float hi) {
    u64 r; asm("mov.b64 %0, {%1, %2};" : "=l"(r) : "f"(lo), "f"(hi)); return r;
}
__device__ __forceinline__ void unpack2(u64 v, float& lo, float& hi) {
    asm("mov.b64 {%0, %1}, %2;" : "=f"(lo), "=f"(hi) : "l"(v));
}
__device__ __forceinline__ u64 ffma2(u64 a, u64 b, u64 c) {
    u64 d; asm("fma.rn.f32x2 %0, %1, %2, %3;" : "=l"(d) : "l"(a), "l"(b), "l"(c)); return d;
}
__device__ __forceinline__ u64 fadd2(u64 a, u64 b) {
    u64 d; asm("add.rn.f32x2 %0, %1, %2;" : "=l"(d) : "l"(a), "l"(b)); return d;
}

// ---- device scratch (no allocations allowed) ----
// Weights stored PRE-DUPLICATED as u64 {w,w}: one LDG.64, zero packing movs.
__device__ u64    g_qkv_w2[CH * O3];   // [c][o] -> {w,w}
__device__ u64    g_out_w2[CH * CH];   // [c][o] -> {w,w}
__device__ double g_bn_sum[CH];
__device__ double g_bn_sqs[CH];
__device__ float  g_bn_g[CH];
__device__ float  g_bn_b[CH];

__global__ void prep_kernel(const float* __restrict__ qkv_w,
                            const float* __restrict__ out_w) {
    int i = blockIdx.x * blockDim.x + threadIdx.x;
    if (i < O3 * CH) {
        int o = i / CH, c = i % CH;
        float w = qkv_w[i];
        g_qkv_w2[c * O3 + o] = pack2(w, w);
    }
    if (i < CH * CH) {
        int o = i / CH, c = i % CH;
        float w = out_w[i];
        g_out_w2[c * CH + o] = pack2(w, w);
    }
    if (i < CH) { g_bn_sum[i] = 0.0; g_bn_sqs[i] = 0.0; }
}

// Shared memory layout (floats). Row stride 36 floats = 144B (16B aligned).
// Aliasing: ys == xs (same-thread read-then-overwrite); ao == q rows of qk
// (warp h consumes its q rows into registers before overwriting them).
#define XS_OFF   0        // xs [128][36]; later reused as ys
#define QK_OFF   4608     // qk [384][36]; q:0-127 (later reused as ao), k:128-255, v:256-383
#define RP_OFF   18432    // rp [4][63]
#define SMEM_FLOATS 18688 // 74,752 bytes -> 3 CTAs/SM

__global__ void __launch_bounds__(128, 3)
attn_kernel(const float* __restrict__ x,
            const float* __restrict__ qkv_b,
            const float* __restrict__ out_b,
            const float* __restrict__ remb,
            float* __restrict__ out) {
    extern __shared__ float sm[];
    float* xs = sm + XS_OFF;
    float* qk = sm + QK_OFF;
    float* ao = sm + QK_OFF;   // aliases q rows (0..127) of qk
    float* ys = sm + XS_OFF;   // aliases xs
    float* rp = sm + RP_OFF;

    const int tid  = threadIdx.x;
    const int lane = tid & 31;
    const int wid  = tid >> 5;
    const int b    = blockIdx.x;

    // ---- stage x[b] into smem ----
    const float4* xg = (const float4*)(x + (size_t)b * (CH * NB));
#pragma unroll
    for (int k = 0; k < 8; k++) {
        int f = tid + k * 128;
        float4 v = xg[f];
        int c = f >> 3, n4 = f & 7;
        *(float4*)(xs + c * 36 + n4 * 4) = v;
    }
    for (int i = tid; i < (2 * NB - 1) * NH; i += 128) {
        int p = i >> 2, h = i & 3;
        rp[h * 63 + p] = remb[i];
    }
    __syncthreads();

    // ---- Phase A (fused q/k/v): one pass over c; 8 LDS feed 48 FFMA2 ----
    // Weight loads software-pipelined one iteration ahead.
    {
        const int o = wid * 32 + lane;           // q row; k = o+128; v = o+256
        u64 accq[16], acck[16], accv[16];
        {
            float bq = qkv_b[o], bk = qkv_b[o + 128], bv = qkv_b[o + 256];
            u64 q2 = pack2(bq, bq), k2 = pack2(bk, bk), v2 = pack2(bv, bv);
#pragma unroll
            for (int j = 0; j < 16; j++) { accq[j] = q2; acck[j] = k2; accv[j] = v2; }
        }
        u64 nwq = g_qkv_w2[o];
        u64 nwk = g_qkv_w2[o + 128];
        u64 nwv = g_qkv_w2[o + 256];
#pragma unroll 2
        for (int c = 0; c < CH; c++) {
            u64 wq = nwq, wk = nwk, wv = nwv;
            if (c + 1 < CH) {                          // prefetch next weights
                nwq = g_qkv_w2[(c + 1) * O3 + o];
                nwk = g_qkv_w2[(c + 1) * O3 + o + 128];
                nwv = g_qkv_w2[(c + 1) * O3 + o + 256];
            }
            const ulonglong2* xr = (const ulonglong2*)(xs + c * 36); // LDS.128 bcast
#pragma unroll
            for (int j = 0; j < 8; j++) {
                ulonglong2 xv = xr[j];
                accq[2*j+0] = ffma2(wq, xv.x, accq[2*j+0]);
                accq[2*j+1] = ffma2(wq, xv.y, accq[2*j+1]);
                acck[2*j+0] = ffma2(wk, xv.x, acck[2*j+0]);
                acck[2*j+1] = ffma2(wk, xv.y, acck[2*j+1]);
                accv[2*j+0] = ffma2(wv, xv.x, accv[2*j+0]);
                accv[2*j+1] = ffma2(wv, xv.y, accv[2*j+1]);
            }
        }
        ulonglong2* dq = (ulonglong2*)(qk + o * 36);
        ulonglong2* dk = (ulonglong2*)(qk + (o + 128) * 36);
        ulonglong2* dv = (ulonglong2*)(qk + (o + 256) * 36);
#pragma unroll
        for (int j = 0; j < 8; j++) {
            dq[j] = make_ulonglong2(accq[2*j], accq[2*j+1]);
            dk[j] = make_ulonglong2(acck[2*j], acck[2*j+1]);
            dv[j] = make_ulonglong2(accv[2*j], accv[2*j+1]);
        }
    }
    __syncthreads();

    // ---- Phase B: head h = wid, query bin n = lane ----
    {
        int h = wid;
        float qreg[32];
#pragma unroll
        for (int d = 0; d < 32; d++)
            qreg[d] = qk[(h * 32 + d) * 36 + lane];               // conflict-free
        u64 att2[16];
#pragma unroll
        for (int j = 0; j < 16; j++) att2[j] = 0ull;
#pragma unroll 4
        for (int d = 0; d < 32; d++) {
            u64 qd2 = pack2(qreg[d], qreg[d]);
            const ulonglong2* kr = (const ulonglong2*)(qk + (128 + h * 32 + d) * 36);
#pragma unroll
            for (int j = 0; j < 8; j++) {
                ulonglong2 kv = kr[j];
                att2[2*j+0] = ffma2(qd2, kv.x, att2[2*j+0]);
                att2[2*j+1] = ffma2(qd2, kv.y, att2[2*j+1]);
            }
        }
        float att[32];
#pragma unroll
        for (int j = 0; j < 16; j++) unpack2(att2[j], att[2*j], att[2*j+1]);
#pragma unroll
        for (int m = 0; m < 32; m++) {
            int idx = m - lane + (NB - 1);
            idx = idx < 0 ? 0 : (idx > 2 * NB - 2 ? 2 * NB - 2 : idx);
            att[m] = fmaf(att[m], ATT_SCALE, rp[h * 63 + idx]);
        }
        float mx = att[0];
#pragma unroll
        for (int m = 1; m < 32; m++) mx = fmaxf(mx, att[m]);
        float ssum = 0.0f;
#pragma unroll
        for (int m = 0; m < 32; m++) {
            float e = __expf(att[m] - mx);
            att[m] = e;
            ssum += e;
        }
        float rs = 1.0f / ssum;
#pragma unroll
        for (int m = 0; m < 32; m++) att[m] *= rs;
#pragma unroll
        for (int j = 0; j < 16; j++) att2[j] = pack2(att[2*j], att[2*j+1]);

        // ---- Phase C: ao[h*32+d][n] = sum_m att[m] * v[h,d,m] ----
        // Writes alias this warp's own q rows; q already consumed into qreg.
#pragma unroll 2
        for (int d = 0; d < 32; d++) {
            const ulonglong2* vr = (const ulonglong2*)(qk + (256 + h * 32 + d) * 36);
            u64 sa = 0ull, sb = 0ull;
#pragma unroll
            for (int j = 0; j < 8; j++) {
                ulonglong2 vv = vr[j];
                sa = ffma2(att2[2*j+0], vv.x, sa);
                sb = ffma2(att2[2*j+1], vv.y, sb);
            }
            float a0, a1, b0, b1;
            unpack2(sa, a0, a1); unpack2(sb, b0, b1);
            ao[(h * 32 + d) * 36 + lane] = (a0 + a1) + (b0 + b1);
        }
    }
    __syncthreads();

    // ---- Phase D: y = out_w @ ao + out_b + x ; BN partial stats ----
    // Weight loads software-pipelined one iteration ahead.
    {
        int o = tid;
        float ob = out_b[o];
        u64 acc2[16];
        u64 ob2 = pack2(ob, ob);
#pragma unroll
        for (int j = 0; j < 16; j++) acc2[j] = ob2;
        u64 nw = g_out_w2[o];
#pragma unroll 8
        for (int c = 0; c < CH; c++) {
            u64 w2 = nw;
            if (c + 1 < CH) nw = g_out_w2[(c + 1) * CH + o];   // prefetch
            const ulonglong2* ar = (const ulonglong2*)(ao + c * 36);
#pragma unroll
            for (int j = 0; j < 8; j++) {
                ulonglong2 av = ar[j];
                acc2[2*j+0] = ffma2(w2, av.x, acc2[2*j+0]);
                acc2[2*j+1] = ffma2(w2, av.y, acc2[2*j+1]);
            }
        }
        u64 s1_2 = 0ull, s2_2 = 0ull;
        const ulonglong2* xr = (const ulonglong2*)(xs + o * 36);
        ulonglong2* yd = (ulonglong2*)(ys + o * 36);   // same address: read-then-write
#pragma unroll
        for (int j = 0; j < 8; j++) {
            ulonglong2 xv = xr[j];
            u64 y0 = fadd2(acc2[2*j+0], xv.x);
            u64 y1 = fadd2(acc2[2*j+1], xv.y);
            s1_2 = fadd2(s1_2, fadd2(y0, y1));
            s2_2 = ffma2(y0, y0, s2_2);
            s2_2 = ffma2(y1, y1, s2_2);
            yd[j] = make_ulonglong2(y0, y1);
        }
        float p0, p1, q0, q1;
        unpack2(s1_2, p0, p1); unpack2(s2_2, q0, q1);
        atomicAdd(&g_bn_sum[o], (double)(p0 + p1));
        atomicAdd(&g_bn_sqs[o], (double)(q0 + q1));
    }
    __syncthreads();

    // ---- coalesced write of pre-BN y to gmem ----
    float4* og = (float4*)(out + (size_t)b * (CH * NB));
#pragma unroll
    for (int k = 0; k < 8; k++) {
        int f = tid + k * 128;
        int c = f >> 3, n4 = f & 7;
        og[f] = *(const float4*)(ys + c * 36 + n4 * 4);
    }
}

__global__ void bn_finalize(const float* __restrict__ gamma,
                            const float* __restrict__ beta) {
    int c = threadIdx.x;
    const double cnt = (double)BATCH * NB;
    double mean = g_bn_sum[c] / cnt;
    double var  = g_bn_sqs[c] / cnt - mean * mean;
    double inv  = 1.0 / sqrt(var + 1e-5);
    double g = (double)gamma[c] * inv;
    g_bn_g[c] = (float)g;
    g_bn_b[c] = (float)((double)beta[c] - mean * g);
}

__global__ void bn_apply(float* __restrict__ out) {
    int i = blockIdx.x * blockDim.x + threadIdx.x;
    float4 v = ((const float4*)out)[i];
    int c = (i >> 3) & 127;
    float g = g_bn_g[c], b = g_bn_b[c];
    v.x = fmaf(v.x, g, b);
    v.y = fmaf(v.y, g, b);
    v.z = fmaf(v.z, g, b);
    v.w = fmaf(v.w, g, b);
    ((float4*)out)[i] = v;
}

extern "C" void kernel_launch(void* const* d_in, const int* in_sizes, int n_in,
                              void* d_out, int out_size) {
    const float* x      = (const float*)d_in[0];
    const float* qkv_w  = (const float*)d_in[1];
    const float* qkv_b  = (const float*)d_in[2];
    const float* out_w  = (const float*)d_in[3];
    const float* out_b  = (const float*)d_in[4];
    const float* remb   = (const float*)d_in[5];
    const float* gamma  = (const float*)d_in[6];
    const float* beta   = (const float*)d_in[7];
    float* out = (float*)d_out;

    cudaFuncSetAttribute(attn_kernel, cudaFuncAttributeMaxDynamicSharedMemorySize,
                         SMEM_FLOATS * (int)sizeof(float));

    prep_kernel<<<192, 256>>>(qkv_w, out_w);
    attn_kernel<<<BATCH, 128, SMEM_FLOATS * sizeof(float)>>>(x, qkv_b, out_b, remb, out);
    bn_finalize<<<1, CH>>>(gamma, beta);
    bn_apply<<<(BATCH * CH * NB / 4) / 256, 256>>>(out);
}